// round 13
// baseline (speedup 1.0000x reference)
#include <cuda_runtime.h>
#include <cuda_bf16.h>
#include <cstdint>

#define PK      16
#define NCENT   8192
#define IN_F    64
#define OUT_F   128
#define M_TILE  64
#define NTH     256

// B packed in mma-fragment order (PTX m16n8k16 .col B frag):
// index = k*8192 + wn8*1024 + nt2*512 + sel*256 + lane*8 + r   (u32 units)
__device__ __align__(128) uint32_t g_bfrag[PK * 8 * 2 * 2 * 32 * 8];   // 512KB

// ---------------- smem: geometry results only (no A staging!) ---------------
#define SM_KPTS   0
#define SM_COEF   256                      // 64*16 f32 = 4096
#define SM_SRCS   (SM_COEF + 4096)         // 64*16 int = 4096
#define SM_TOTAL  (SM_SRCS + 4096)         // 8448 bytes

__device__ __forceinline__ void mma_bf16(float* c, const uint32_t* a, const uint32_t* b) {
    asm volatile("mma.sync.aligned.m16n8k16.row.col.f32.bf16.bf16.f32 "
                 "{%0,%1,%2,%3}, {%4,%5,%6,%7}, {%8,%9}, {%0,%1,%2,%3};"
                 : "+f"(c[0]), "+f"(c[1]), "+f"(c[2]), "+f"(c[3])
                 : "r"(a[0]), "r"(a[1]), "r"(a[2]), "r"(a[3]),
                   "r"(b[0]), "r"(b[1]));
}

// ---------------- pre-kernel: W -> fragment-packed hi/lo ---------------------
__global__ void wpack_kernel(const float* __restrict__ w) {
    int idx = blockIdx.x * blockDim.x + threadIdx.x;
    if (idx >= PK * 8 * 2 * 2 * 32 * 8) return;
    int r    = idx & 7;
    int lane = (idx >> 3) & 31;
    int sel  = (idx >> 8) & 1;
    int nt   = (idx >> 9) & 1;
    int wn   = (idx >> 10) & 7;
    int k    = idx >> 13;
    int ks   = r >> 1;
    int pair = r & 1;
    int o = wn * 16 + nt * 8 + (lane >> 2);
    int i = ks * 16 + (lane & 3) * 2 + pair * 8;
    float v0 = w[k * (IN_F * OUT_F) + i * OUT_F + o];
    float v1 = w[k * (IN_F * OUT_F) + (i + 1) * OUT_F + o];
    __nv_bfloat16 h0 = __float2bfloat16(v0);
    __nv_bfloat16 h1 = __float2bfloat16(v1);
    if (sel) {
        h0 = __float2bfloat16(v0 - __bfloat162float(h0));
        h1 = __float2bfloat16(v1 - __bfloat162float(h1));
    }
    __nv_bfloat162 p; p.x = h0; p.y = h1;
    g_bfrag[idx] = *(uint32_t*)&p;
}

// B prefetch: 8 hi then 8 lo uint4
__device__ __forceinline__ void b_prefetch(uint4 (&b)[16], const uint32_t* bb) {
    b[0]  = *(const uint4*)(bb + 0);    b[1]  = *(const uint4*)(bb + 4);
    b[2]  = *(const uint4*)(bb + 512);  b[3]  = *(const uint4*)(bb + 516);
    b[4]  = *(const uint4*)(bb + 1024); b[5]  = *(const uint4*)(bb + 1028);
    b[6]  = *(const uint4*)(bb + 1536); b[7]  = *(const uint4*)(bb + 1540);
    b[8]  = *(const uint4*)(bb + 256);  b[9]  = *(const uint4*)(bb + 260);
    b[10] = *(const uint4*)(bb + 768);  b[11] = *(const uint4*)(bb + 772);
    b[12] = *(const uint4*)(bb + 1280); b[13] = *(const uint4*)(bb + 1284);
    b[14] = *(const uint4*)(bb + 1792); b[15] = *(const uint4*)(bb + 1796);
}

__device__ __forceinline__ uint32_t pack_split(float f0, float f1, uint32_t& lo) {
    __nv_bfloat16 h0 = __float2bfloat16(f0);
    __nv_bfloat16 h1 = __float2bfloat16(f1);
    __nv_bfloat162 hp; hp.x = h0; hp.y = h1;
    __nv_bfloat162 lp;
    lp.x = __float2bfloat16(f0 - __bfloat162float(h0));
    lp.y = __float2bfloat16(f1 - __bfloat162float(h1));
    lo = *(uint32_t*)&lp;
    return *(uint32_t*)&hp;
}

// 8 float2 A-loads for one 16-col slice (cols in float units)
#define A_LOAD(dst, c0)                                                     \
    do {                                                                    \
        _Pragma("unroll")                                                   \
        for (int mt = 0; mt < 2; mt++) {                                    \
            dst[mt*4+0] = *(const float2*)(rp[2*mt]   + (c0));              \
            dst[mt*4+1] = *(const float2*)(rp[2*mt+1] + (c0));              \
            dst[mt*4+2] = *(const float2*)(rp[2*mt]   + (c0) + 8);          \
            dst[mt*4+3] = *(const float2*)(rp[2*mt+1] + (c0) + 8);          \
        }                                                                   \
    } while (0)

__device__ __forceinline__ void gemm_step(
    int k, uint4 (&bcur)[16], uint4 (&bnxt)[16],
    const float* __restrict__ x, const int* s_srcs, const float* s_coef,
    const int (&rows)[4], int cpair, int wnp, int lane,
    float (&acc)[2][4][4])
{
    // B[k+1] prefetch (in flight across this whole step)
    if (k + 1 < PK)
        b_prefetch(bnxt, g_bfrag + (k + 1) * 8192 + wnp * 2048 + lane * 8);

    // per-row source pointers + scales for this k
    const float* rp[4];
    float cf[4];
    #pragma unroll
    for (int j = 0; j < 4; j++) {
        int r = rows[j];
        rp[j] = x + (size_t)s_srcs[r * PK + k] * IN_F;
        cf[j] = s_coef[r * PK + k];
    }

    float2 af[8], ag[8];
    A_LOAD(af, cpair);                     // ks = 0

    #pragma unroll
    for (int ks = 0; ks < 4; ks++) {
        if (ks < 3) A_LOAD(ag, (ks + 1) * 16 + cpair);   // next slice in flight

        // scale + hi/lo split, straight into fragment registers
        uint32_t ah[2][4], al[2][4];
        #pragma unroll
        for (int mt = 0; mt < 2; mt++)
            #pragma unroll
            for (int q = 0; q < 4; q++) {
                float sc = cf[2 * mt + (q & 1)];
                ah[mt][q] = pack_split(af[mt*4+q].x * sc, af[mt*4+q].y * sc,
                                       al[mt][q]);
            }

        #pragma unroll
        for (int mt = 0; mt < 2; mt++)
            #pragma unroll
            for (int nt = 0; nt < 4; nt++) {
                const uint4& BH = bcur[2 * nt + (ks >> 1)];
                const uint4& BL = bcur[8 + 2 * nt + (ks >> 1)];
                uint32_t bh2[2], bl2[2];
                if (ks & 1) { bh2[0] = BH.z; bh2[1] = BH.w;
                              bl2[0] = BL.z; bl2[1] = BL.w; }
                else        { bh2[0] = BH.x; bh2[1] = BH.y;
                              bl2[0] = BL.x; bl2[1] = BL.y; }
                mma_bf16(acc[mt][nt], ah[mt], bh2);
                mma_bf16(acc[mt][nt], ah[mt], bl2);
                mma_bf16(acc[mt][nt], al[mt], bh2);
            }

        #pragma unroll
        for (int q = 0; q < 8; q++) af[q] = ag[q];
    }
}

// ---------------- main fused kernel ------------------------------------------
__global__ __launch_bounds__(NTH, 1) void kpconv_hmma_kernel(
    const float* __restrict__ x,
    const float* __restrict__ pos,
    const int*   __restrict__ edge_src,
    const int*   __restrict__ edge_tgt,
    const float* __restrict__ kernel_pts,
    float* __restrict__ out)
{
    extern __shared__ char sm[];
    float* s_kpts = (float*)(sm + SM_KPTS);
    float* s_coef = (float*)(sm + SM_COEF);
    int*   s_srcs = (int*)(sm + SM_SRCS);

    const int tid  = threadIdx.x;
    const int wid  = tid >> 5;
    const int lane = tid & 31;
    const int c0c  = blockIdx.x * M_TILE;

    if (tid < PK * 3) s_kpts[tid] = kernel_pts[tid];
    for (int i = tid; i < M_TILE * PK; i += NTH) s_coef[i] = 0.0f;
    __syncthreads();

    // ---- geometry: argmin kernel point + linear influence -> coef/srcs -----
    #pragma unroll
    for (int j = 0; j < (M_TILE * PK) / NTH; j++) {
        int el = tid + j * NTH;
        int e  = c0c * PK + el;
        int s  = edge_src[e];
        int t  = edge_tgt[e];
        s_srcs[el] = s;
        float rx = pos[3 * t + 0] - pos[3 * s + 0];
        float ry = pos[3 * t + 1] - pos[3 * s + 1];
        float rz = pos[3 * t + 2] - pos[3 * s + 2];
        float best = 3.4e38f; int bk = 0;
        #pragma unroll
        for (int kp = 0; kp < PK; kp++) {
            float dx = rx - s_kpts[3 * kp + 0];
            float dy = ry - s_kpts[3 * kp + 1];
            float dz = rz - s_kpts[3 * kp + 2];
            float d2 = dx * dx + dy * dy + dz * dz;
            if (d2 < best) { best = d2; bk = kp; }
        }
        float w = fmaxf(1.0f - sqrtf(best) * 1.5f, 0.0f);   // 1/KP_EXTENT = 1.5
        atomicAdd(&s_coef[(el & ~(PK - 1)) + bk], w);
    }
    __syncthreads();     // ONLY barrier before epilogue — mainloop is sync-free

    // 8 warps: wm = wid&1 (2 x 32 rows), wnp = wid>>1 (4 x 32 cols)
    const int wm  = wid & 1;
    const int wnp = wid >> 1;
    const int g   = lane >> 2;
    const int cpair = (lane & 3) * 2;

    int rows[4];
    #pragma unroll
    for (int j = 0; j < 4; j++) rows[j] = wm * 32 + j * 8 + g;

    float acc[2][4][4];
    #pragma unroll
    for (int mt = 0; mt < 2; mt++)
        #pragma unroll
        for (int nt = 0; nt < 4; nt++)
            #pragma unroll
            for (int q = 0; q < 4; q++) acc[mt][nt][q] = 0.0f;

    uint4 b0[16], b1[16];
    b_prefetch(b0, g_bfrag + wnp * 2048 + lane * 8);   // B[0]

    #pragma unroll 1
    for (int kk = 0; kk < PK; kk += 2) {
        gemm_step(kk,     b0, b1, x, s_srcs, s_coef, rows, cpair, wnp, lane, acc);
        gemm_step(kk + 1, b1, b0, x, s_srcs, s_coef, rows, cpair, wnp, lane, acc);
    }

    // ---- epilogue: direct f32 stores ----------------------------------------
    #pragma unroll
    for (int mt = 0; mt < 2; mt++) {
        int row = c0c + wm * 32 + mt * 16 + (lane >> 2);
        #pragma unroll
        for (int nt = 0; nt < 4; nt++) {
            int col = wnp * 32 + nt * 8 + (lane & 3) * 2;
            float2 v0 = make_float2(acc[mt][nt][0], acc[mt][nt][1]);
            float2 v1 = make_float2(acc[mt][nt][2], acc[mt][nt][3]);
            *(float2*)(out + (size_t)row * OUT_F + col)       = v0;
            *(float2*)(out + (size_t)(row + 8) * OUT_F + col) = v1;
        }
    }
}

extern "C" void kernel_launch(void* const* d_in, const int* in_sizes, int n_in,
                              void* d_out, int out_size) {
    const float* x             = (const float*)d_in[0];
    const float* pos           = (const float*)d_in[1];
    const int*   edge_src      = (const int*)d_in[2];
    const int*   edge_tgt      = (const int*)d_in[3];
    const float* kernel_pts    = (const float*)d_in[4];
    const float* kernel_weight = (const float*)d_in[5];
    float* out = (float*)d_out;

    wpack_kernel<<<(PK * 8 * 2 * 2 * 32 * 8 + 255) / 256, 256>>>(kernel_weight);

    cudaFuncSetAttribute(kpconv_hmma_kernel,
                         cudaFuncAttributeMaxDynamicSharedMemorySize, SM_TOTAL);
    kpconv_hmma_kernel<<<NCENT / M_TILE, NTH, SM_TOTAL>>>(
        x, pos, edge_src, edge_tgt, kernel_pts, out);
}

// round 14
// speedup vs baseline: 1.3872x; 1.3872x over previous
#include <cuda_runtime.h>
#include <cuda_fp16.h>
#include <cstdint>

#define PK      16
#define NCENT   8192
#define IN_F    64
#define OUT_F   128
#define M_TILE  32
#define NTH     128
#define LDB     144          // A smem row pitch bytes (64 fp16 + 8 pad)

// B packed in mma-fragment order (PTX m16n8k16 .col B frag), fp16 hi/lo:
// index = k*8192 + wn8*1024 + nt2*512 + sel*256 + lane*8 + r   (u32 units)
__device__ __align__(128) uint32_t g_bfrag[PK * 8 * 2 * 2 * 32 * 8];   // 512KB

// ---------------- smem layout (bytes): A(hi only) double-buffered ------------
#define SM_KPTS   0
#define SM_COEF   256                      // 32*16 f32 = 2048
#define SM_SRCS   (SM_COEF + 2048)         // 32*16 int = 2048
#define SM_A      4352
#define A_BYTES   (M_TILE * LDB)           // 4608
#define AH_OFF(s) (SM_A + (s) * A_BYTES)
#define SM_TOTAL  (SM_A + 2 * A_BYTES)     // 13568

__device__ __forceinline__ uint32_t smem_u32(const void* p) {
    uint32_t a;
    asm("{ .reg .u64 t; cvta.to.shared.u64 t, %1; cvt.u32.u64 %0, t; }"
        : "=r"(a) : "l"(p));
    return a;
}
__device__ __forceinline__ void ldsm4(uint32_t* r, uint32_t addr) {
    asm volatile("ldmatrix.sync.aligned.m8n8.x4.shared.b16 {%0,%1,%2,%3}, [%4];"
                 : "=r"(r[0]), "=r"(r[1]), "=r"(r[2]), "=r"(r[3]) : "r"(addr));
}
__device__ __forceinline__ void mma_f16(float* c, const uint32_t* a, const uint32_t* b) {
    asm volatile("mma.sync.aligned.m16n8k16.row.col.f32.f16.f16.f32 "
                 "{%0,%1,%2,%3}, {%4,%5,%6,%7}, {%8,%9}, {%0,%1,%2,%3};"
                 : "+f"(c[0]), "+f"(c[1]), "+f"(c[2]), "+f"(c[3])
                 : "r"(a[0]), "r"(a[1]), "r"(a[2]), "r"(a[3]),
                   "r"(b[0]), "r"(b[1]));
}

// ---------------- pre-kernel: W -> fragment-packed fp16 hi/lo ----------------
__global__ void wpack_kernel(const float* __restrict__ w) {
    int idx = blockIdx.x * blockDim.x + threadIdx.x;
    if (idx >= PK * 8 * 2 * 2 * 32 * 8) return;
    int r    = idx & 7;
    int lane = (idx >> 3) & 31;
    int sel  = (idx >> 8) & 1;
    int nt   = (idx >> 9) & 1;
    int wn   = (idx >> 10) & 7;
    int k    = idx >> 13;
    int ks   = r >> 1;
    int pair = r & 1;
    int o = wn * 16 + nt * 8 + (lane >> 2);
    int i = ks * 16 + (lane & 3) * 2 + pair * 8;
    float v0 = w[k * (IN_F * OUT_F) + i * OUT_F + o];
    float v1 = w[k * (IN_F * OUT_F) + (i + 1) * OUT_F + o];
    __half h0 = __float2half(v0);
    __half h1 = __float2half(v1);
    if (sel) {
        h0 = __float2half(v0 - __half2float(h0));
        h1 = __float2half(v1 - __half2float(h1));
    }
    __half2 p; p.x = h0; p.y = h1;
    g_bfrag[idx] = *(uint32_t*)&p;
}

// A staging: thread owns row arow = tid>>2 (0..31), 16-float quarter aq = tid&3
// fp16 single precision (hi only)
#define A_CVT_STORE(stage)                                                  \
    do {                                                                    \
        float fv[16];                                                       \
        _Pragma("unroll")                                                   \
        for (int j = 0; j < 4; j++) {                                       \
            fv[j*4+0] = av[j].x * asc; fv[j*4+1] = av[j].y * asc;           \
            fv[j*4+2] = av[j].z * asc; fv[j*4+3] = av[j].w * asc;           \
        }                                                                   \
        uint32_t hi[8];                                                     \
        _Pragma("unroll")                                                   \
        for (int e2 = 0; e2 < 8; e2++) {                                    \
            __half2 hp;                                                     \
            hp.x = __float2half(fv[e2 * 2]);                                \
            hp.y = __float2half(fv[e2 * 2 + 1]);                            \
            hi[e2] = *(uint32_t*)&hp;                                       \
        }                                                                   \
        *(uint4*)(sm + AH_OFF(stage) + arow * LDB + aq * 32) =              \
            make_uint4(hi[0], hi[1], hi[2], hi[3]);                         \
        *(uint4*)(sm + AH_OFF(stage) + arow * LDB + aq * 32 + 16) =         \
            make_uint4(hi[4], hi[5], hi[6], hi[7]);                         \
    } while (0)

// B prefetch offsets (u32 units): 8 hi then 8 lo uint4
__device__ __forceinline__ void b_prefetch(uint4 (&b)[16], const uint32_t* bb) {
    b[0]  = *(const uint4*)(bb + 0);    b[1]  = *(const uint4*)(bb + 4);
    b[2]  = *(const uint4*)(bb + 512);  b[3]  = *(const uint4*)(bb + 516);
    b[4]  = *(const uint4*)(bb + 1024); b[5]  = *(const uint4*)(bb + 1028);
    b[6]  = *(const uint4*)(bb + 1536); b[7]  = *(const uint4*)(bb + 1540);
    b[8]  = *(const uint4*)(bb + 256);  b[9]  = *(const uint4*)(bb + 260);
    b[10] = *(const uint4*)(bb + 768);  b[11] = *(const uint4*)(bb + 772);
    b[12] = *(const uint4*)(bb + 1280); b[13] = *(const uint4*)(bb + 1284);
    b[14] = *(const uint4*)(bb + 1792); b[15] = *(const uint4*)(bb + 1796);
}

struct StepCtx {
    char* sm; uint32_t smb;
    const float* x; const int* s_srcs; const float* s_coef;
    int arow, aq, wnp, lane;
    uint32_t a_row_off0, a_row_off1;
};

__device__ __forceinline__ void gemm_step(
    int k, uint4 (&bcur)[16], uint4 (&bnxt)[16],
    const StepCtx& c, float4 (&av)[4], float& asc,
    float (&acc)[2][4][4])
{
    char* sm = c.sm;
    const int arow = c.arow, aq = c.aq;
    const int cur = k & 1;

    // prefetch A[k+1] + B[k+1] (LDGs outstanding across compute)
    if (k + 1 < PK) {
        int src = c.s_srcs[arow * PK + k + 1];
        asc = c.s_coef[arow * PK + k + 1];
        const float4* xp = (const float4*)(c.x + (size_t)src * IN_F + aq * 16);
        #pragma unroll
        for (int j = 0; j < 4; j++) av[j] = xp[j];
        b_prefetch(bnxt, g_bfrag + (k + 1) * 8192 + c.wnp * 2048 + c.lane * 8);
    }

    // unpack current B fragments (register aliases)
    uint32_t bh[4][8], bl[4][8];
    #pragma unroll
    for (int j = 0; j < 4; j++) {
        bh[j][0] = bcur[2*j].x;   bh[j][1] = bcur[2*j].y;
        bh[j][2] = bcur[2*j].z;   bh[j][3] = bcur[2*j].w;
        bh[j][4] = bcur[2*j+1].x; bh[j][5] = bcur[2*j+1].y;
        bh[j][6] = bcur[2*j+1].z; bh[j][7] = bcur[2*j+1].w;
        bl[j][0] = bcur[8+2*j].x;   bl[j][1] = bcur[8+2*j].y;
        bl[j][2] = bcur[8+2*j].z;   bl[j][3] = bcur[8+2*j].w;
        bl[j][4] = bcur[8+2*j+1].x; bl[j][5] = bcur[8+2*j+1].y;
        bl[j][6] = bcur[8+2*j+1].z; bl[j][7] = bcur[8+2*j+1].w;
    }

    const uint32_t ah_b = c.smb + AH_OFF(cur);
    const uint32_t aro[2] = {c.a_row_off0, c.a_row_off1};
    #pragma unroll
    for (int ks = 0; ks < 4; ks++) {
        const uint32_t i0 = ks * 32;
        uint32_t ah[2][4];
        #pragma unroll
        for (int mt = 0; mt < 2; mt++)
            ldsm4(ah[mt], ah_b + aro[mt] + i0);
        #pragma unroll
        for (int mt = 0; mt < 2; mt++)
            #pragma unroll
            for (int nt = 0; nt < 4; nt++) {
                mma_f16(acc[mt][nt], ah[mt], &bh[nt][ks * 2]);
                mma_f16(acc[mt][nt], ah[mt], &bl[nt][ks * 2]);
            }
    }

    if (k + 1 < PK) A_CVT_STORE(cur ^ 1);
    __syncthreads();
}

// ---------------- main fused kernel ------------------------------------------
__global__ __launch_bounds__(NTH, 2) void kpconv_hmma_kernel(
    const float* __restrict__ x,
    const float* __restrict__ pos,
    const int*   __restrict__ edge_src,
    const int*   __restrict__ edge_tgt,
    const float* __restrict__ kernel_pts,
    float* __restrict__ out)
{
    extern __shared__ char sm[];
    const uint32_t smb = smem_u32(sm);
    float* s_kpts = (float*)(sm + SM_KPTS);
    float* s_coef = (float*)(sm + SM_COEF);
    int*   s_srcs = (int*)(sm + SM_SRCS);

    const int tid  = threadIdx.x;
    const int wid  = tid >> 5;
    const int lane = tid & 31;
    const int c0   = blockIdx.x * M_TILE;

    if (tid < PK * 3) s_kpts[tid] = kernel_pts[tid];
    for (int i = tid; i < M_TILE * PK; i += NTH) s_coef[i] = 0.0f;
    __syncthreads();

    // ---- geometry: argmin kernel point + linear influence -> coef/srcs -----
    #pragma unroll
    for (int j = 0; j < (M_TILE * PK) / NTH; j++) {
        int el = tid + j * NTH;
        int e  = c0 * PK + el;
        int s  = edge_src[e];
        int t  = edge_tgt[e];
        s_srcs[el] = s;
        float rx = pos[3 * t + 0] - pos[3 * s + 0];
        float ry = pos[3 * t + 1] - pos[3 * s + 1];
        float rz = pos[3 * t + 2] - pos[3 * s + 2];
        float best = 3.4e38f; int bk = 0;
        #pragma unroll
        for (int kp = 0; kp < PK; kp++) {
            float dx = rx - s_kpts[3 * kp + 0];
            float dy = ry - s_kpts[3 * kp + 1];
            float dz = rz - s_kpts[3 * kp + 2];
            float d2 = dx * dx + dy * dy + dz * dz;
            if (d2 < best) { best = d2; bk = kp; }
        }
        float w = fmaxf(1.0f - sqrtf(best) * 1.5f, 0.0f);   // 1/KP_EXTENT = 1.5
        atomicAdd(&s_coef[(el & ~(PK - 1)) + bk], w);
    }
    __syncthreads();

    // 4 warps, each owns all 32 rows x 32 cols (wnp = wid)
    const int wnp = wid;

    StepCtx ctx;
    ctx.sm = sm; ctx.smb = smb;
    ctx.x = x; ctx.s_srcs = s_srcs; ctx.s_coef = s_coef;
    ctx.arow = tid >> 2; ctx.aq = tid & 3; ctx.wnp = wnp; ctx.lane = lane;
    ctx.a_row_off0 = (uint32_t)((0  + (lane & 15)) * LDB + (lane >> 4) * 16);
    ctx.a_row_off1 = (uint32_t)((16 + (lane & 15)) * LDB + (lane >> 4) * 16);

    float acc[2][4][4];
    #pragma unroll
    for (int mt = 0; mt < 2; mt++)
        #pragma unroll
        for (int nt = 0; nt < 4; nt++)
            #pragma unroll
            for (int q = 0; q < 4; q++) acc[mt][nt][q] = 0.0f;

    const int arow = ctx.arow, aq = ctx.aq;
    float4 av[4];
    float  asc;
    uint4  b0[16], b1[16];

    // prologue: A[0] staged, B[0] -> b0
    {
        int src = s_srcs[arow * PK + 0];
        asc = s_coef[arow * PK + 0];
        const float4* xp = (const float4*)(x + (size_t)src * IN_F + aq * 16);
        #pragma unroll
        for (int j = 0; j < 4; j++) av[j] = xp[j];
        b_prefetch(b0, g_bfrag + wnp * 2048 + lane * 8);
        A_CVT_STORE(0);
    }
    __syncthreads();

    #pragma unroll 1
    for (int kk = 0; kk < PK; kk += 2) {
        gemm_step(kk,     b0, b1, ctx, av, asc, acc);
        gemm_step(kk + 1, b1, b0, ctx, av, asc, acc);
    }

    // ---- epilogue ----
    #pragma unroll
    for (int mt = 0; mt < 2; mt++) {
        int row = c0 + mt * 16 + (lane >> 2);
        #pragma unroll
        for (int nt = 0; nt < 4; nt++) {
            int col = wnp * 32 + nt * 8 + (lane & 3) * 2;
            float2 v0 = make_float2(acc[mt][nt][0], acc[mt][nt][1]);
            float2 v1 = make_float2(acc[mt][nt][2], acc[mt][nt][3]);
            *(float2*)(out + (size_t)row * OUT_F + col)       = v0;
            *(float2*)(out + (size_t)(row + 8) * OUT_F + col) = v1;
        }
    }
}

extern "C" void kernel_launch(void* const* d_in, const int* in_sizes, int n_in,
                              void* d_out, int out_size) {
    const float* x             = (const float*)d_in[0];
    const float* pos           = (const float*)d_in[1];
    const int*   edge_src      = (const int*)d_in[2];
    const int*   edge_tgt      = (const int*)d_in[3];
    const float* kernel_pts    = (const float*)d_in[4];
    const float* kernel_weight = (const float*)d_in[5];
    float* out = (float*)d_out;

    wpack_kernel<<<(PK * 8 * 2 * 2 * 32 * 8 + 255) / 256, 256>>>(kernel_weight);

    cudaFuncSetAttribute(kpconv_hmma_kernel,
                         cudaFuncAttributeMaxDynamicSharedMemorySize, SM_TOTAL);
    kpconv_hmma_kernel<<<NCENT / M_TILE, NTH, SM_TOTAL>>>(
        x, pos, edge_src, edge_tgt, kernel_pts, out);
}

// round 15
// speedup vs baseline: 1.6140x; 1.1635x over previous
#include <cuda_runtime.h>
#include <cuda_fp16.h>
#include <cstdint>

#define PK      16
#define NCENT   8192
#define IN_F    64
#define OUT_F   128
#define M_TILE  32
#define NTH     128
#define LDB     144          // A smem row pitch bytes (64 fp16 + 8 pad)

// B packed in mma-fragment order (PTX m16n8k16 .col B frag), fp16 single:
// index = k*4096 + wn4*1024 + nt4*256 + lane*8 + r   (u32 units)
//   r = ks*2 + pair; element = half2{ W[k][i][o], W[k][i+1][o] }
//   o = wn*32 + nt*8 + (lane>>2);  i = ks*16 + (lane&3)*2 + pair*8
__device__ __align__(128) uint32_t g_bfrag[PK * 4 * 4 * 32 * 8];   // 256KB

// ---------------- smem layout (bytes): A(hi only) double-buffered ------------
#define SM_KPTS   0
#define SM_COEF   256                      // 32*16 f32 = 2048
#define SM_SRCS   (SM_COEF + 2048)         // 32*16 int = 2048
#define SM_A      4352
#define A_BYTES   (M_TILE * LDB)           // 4608
#define AH_OFF(s) (SM_A + (s) * A_BYTES)
#define SM_TOTAL  (SM_A + 2 * A_BYTES)     // 13568

__device__ __forceinline__ uint32_t smem_u32(const void* p) {
    uint32_t a;
    asm("{ .reg .u64 t; cvta.to.shared.u64 t, %1; cvt.u32.u64 %0, t; }"
        : "=r"(a) : "l"(p));
    return a;
}
__device__ __forceinline__ void ldsm4(uint32_t* r, uint32_t addr) {
    asm volatile("ldmatrix.sync.aligned.m8n8.x4.shared.b16 {%0,%1,%2,%3}, [%4];"
                 : "=r"(r[0]), "=r"(r[1]), "=r"(r[2]), "=r"(r[3]) : "r"(addr));
}
__device__ __forceinline__ void mma_f16(float* c, const uint32_t* a, const uint32_t* b) {
    asm volatile("mma.sync.aligned.m16n8k16.row.col.f32.f16.f16.f32 "
                 "{%0,%1,%2,%3}, {%4,%5,%6,%7}, {%8,%9}, {%0,%1,%2,%3};"
                 : "+f"(c[0]), "+f"(c[1]), "+f"(c[2]), "+f"(c[3])
                 : "r"(a[0]), "r"(a[1]), "r"(a[2]), "r"(a[3]),
                   "r"(b[0]), "r"(b[1]));
}

// ---------------- pre-kernel: W -> fragment-packed fp16 ----------------------
__global__ void wpack_kernel(const float* __restrict__ w) {
    int idx = blockIdx.x * blockDim.x + threadIdx.x;
    if (idx >= PK * 4 * 4 * 32 * 8) return;     // 65536
    int r    = idx & 7;
    int lane = (idx >> 3) & 31;
    int nt   = (idx >> 8) & 3;
    int wn   = (idx >> 10) & 3;
    int k    = idx >> 12;
    int ks   = r >> 1;
    int pair = r & 1;
    int o = wn * 32 + nt * 8 + (lane >> 2);
    int i = ks * 16 + (lane & 3) * 2 + pair * 8;
    float v0 = w[k * (IN_F * OUT_F) + i * OUT_F + o];
    float v1 = w[k * (IN_F * OUT_F) + (i + 1) * OUT_F + o];
    __half2 p; p.x = __float2half(v0); p.y = __float2half(v1);
    g_bfrag[idx] = *(uint32_t*)&p;
}

// A staging: thread owns row arow = tid>>2 (0..31), 16-float quarter aq = tid&3
#define A_CVT_STORE(stage)                                                  \
    do {                                                                    \
        float fv[16];                                                       \
        _Pragma("unroll")                                                   \
        for (int j = 0; j < 4; j++) {                                       \
            fv[j*4+0] = av[j].x * asc; fv[j*4+1] = av[j].y * asc;           \
            fv[j*4+2] = av[j].z * asc; fv[j*4+3] = av[j].w * asc;           \
        }                                                                   \
        uint32_t hi[8];                                                     \
        _Pragma("unroll")                                                   \
        for (int e2 = 0; e2 < 8; e2++) {                                    \
            __half2 hp;                                                     \
            hp.x = __float2half(fv[e2 * 2]);                                \
            hp.y = __float2half(fv[e2 * 2 + 1]);                            \
            hi[e2] = *(uint32_t*)&hp;                                       \
        }                                                                   \
        *(uint4*)(sm + AH_OFF(stage) + arow * LDB + aq * 32) =              \
            make_uint4(hi[0], hi[1], hi[2], hi[3]);                         \
        *(uint4*)(sm + AH_OFF(stage) + arow * LDB + aq * 32 + 16) =         \
            make_uint4(hi[4], hi[5], hi[6], hi[7]);                         \
    } while (0)

// B prefetch: 8 uint4 = 4 nt-tiles x (8 u32)
__device__ __forceinline__ void b_prefetch(uint4 (&b)[8], const uint32_t* bb) {
    b[0] = *(const uint4*)(bb + 0);    b[1] = *(const uint4*)(bb + 4);
    b[2] = *(const uint4*)(bb + 256);  b[3] = *(const uint4*)(bb + 260);
    b[4] = *(const uint4*)(bb + 512);  b[5] = *(const uint4*)(bb + 516);
    b[6] = *(const uint4*)(bb + 768);  b[7] = *(const uint4*)(bb + 772);
}

struct StepCtx {
    char* sm; uint32_t smb;
    const float* x; const int* s_srcs; const float* s_coef;
    int arow, aq, wnp, lane;
    uint32_t a_row_off0, a_row_off1;
};

__device__ __forceinline__ void gemm_step(
    int k, uint4 (&bcur)[8], uint4 (&bnxt)[8],
    const StepCtx& c, float4 (&av)[4], float& asc,
    float (&acc)[2][4][4])
{
    char* sm = c.sm;
    const int arow = c.arow, aq = c.aq;
    const int cur = k & 1;

    // prefetch A[k+1] + B[k+1] (LDGs outstanding across compute)
    if (k + 1 < PK) {
        int src = c.s_srcs[arow * PK + k + 1];
        asc = c.s_coef[arow * PK + k + 1];
        const float4* xp = (const float4*)(c.x + (size_t)src * IN_F + aq * 16);
        #pragma unroll
        for (int j = 0; j < 4; j++) av[j] = xp[j];
        b_prefetch(bnxt, g_bfrag + (k + 1) * 4096 + c.wnp * 1024 + c.lane * 8);
    }

    // unpack current B fragments (register aliases)
    uint32_t bh[4][8];
    #pragma unroll
    for (int j = 0; j < 4; j++) {
        bh[j][0] = bcur[2*j].x;   bh[j][1] = bcur[2*j].y;
        bh[j][2] = bcur[2*j].z;   bh[j][3] = bcur[2*j].w;
        bh[j][4] = bcur[2*j+1].x; bh[j][5] = bcur[2*j+1].y;
        bh[j][6] = bcur[2*j+1].z; bh[j][7] = bcur[2*j+1].w;
    }

    const uint32_t ah_b = c.smb + AH_OFF(cur);
    const uint32_t aro[2] = {c.a_row_off0, c.a_row_off1};
    #pragma unroll
    for (int ks = 0; ks < 4; ks++) {
        const uint32_t i0 = ks * 32;
        uint32_t ah[2][4];
        #pragma unroll
        for (int mt = 0; mt < 2; mt++)
            ldsm4(ah[mt], ah_b + aro[mt] + i0);
        #pragma unroll
        for (int mt = 0; mt < 2; mt++)
            #pragma unroll
            for (int nt = 0; nt < 4; nt++)
                mma_f16(acc[mt][nt], ah[mt], &bh[nt][ks * 2]);
    }

    if (k + 1 < PK) A_CVT_STORE(cur ^ 1);
    __syncthreads();
}

// ---------------- main fused kernel ------------------------------------------
__global__ __launch_bounds__(NTH, 3) void kpconv_hmma_kernel(
    const float* __restrict__ x,
    const float* __restrict__ pos,
    const int*   __restrict__ edge_src,
    const int*   __restrict__ edge_tgt,
    const float* __restrict__ kernel_pts,
    float* __restrict__ out)
{
    extern __shared__ char sm[];
    const uint32_t smb = smem_u32(sm);
    float* s_kpts = (float*)(sm + SM_KPTS);
    float* s_coef = (float*)(sm + SM_COEF);
    int*   s_srcs = (int*)(sm + SM_SRCS);

    const int tid  = threadIdx.x;
    const int wid  = tid >> 5;
    const int lane = tid & 31;
    const int c0   = blockIdx.x * M_TILE;

    if (tid < PK * 3) s_kpts[tid] = kernel_pts[tid];
    for (int i = tid; i < M_TILE * PK; i += NTH) s_coef[i] = 0.0f;
    __syncthreads();

    // ---- geometry: argmin kernel point + linear influence -> coef/srcs -----
    #pragma unroll
    for (int j = 0; j < (M_TILE * PK) / NTH; j++) {
        int el = tid + j * NTH;
        int e  = c0 * PK + el;
        int s  = edge_src[e];
        int t  = edge_tgt[e];
        s_srcs[el] = s;
        float rx = pos[3 * t + 0] - pos[3 * s + 0];
        float ry = pos[3 * t + 1] - pos[3 * s + 1];
        float rz = pos[3 * t + 2] - pos[3 * s + 2];
        float best = 3.4e38f; int bk = 0;
        #pragma unroll
        for (int kp = 0; kp < PK; kp++) {
            float dx = rx - s_kpts[3 * kp + 0];
            float dy = ry - s_kpts[3 * kp + 1];
            float dz = rz - s_kpts[3 * kp + 2];
            float d2 = dx * dx + dy * dy + dz * dz;
            if (d2 < best) { best = d2; bk = kp; }
        }
        float w = fmaxf(1.0f - sqrtf(best) * 1.5f, 0.0f);   // 1/KP_EXTENT = 1.5
        atomicAdd(&s_coef[(el & ~(PK - 1)) + bk], w);
    }
    __syncthreads();

    // 4 warps, each owns all 32 rows x 32 cols (wnp = wid)
    const int wnp = wid;

    StepCtx ctx;
    ctx.sm = sm; ctx.smb = smb;
    ctx.x = x; ctx.s_srcs = s_srcs; ctx.s_coef = s_coef;
    ctx.arow = tid >> 2; ctx.aq = tid & 3; ctx.wnp = wnp; ctx.lane = lane;
    ctx.a_row_off0 = (uint32_t)((0  + (lane & 15)) * LDB + (lane >> 4) * 16);
    ctx.a_row_off1 = (uint32_t)((16 + (lane & 15)) * LDB + (lane >> 4) * 16);

    float acc[2][4][4];
    #pragma unroll
    for (int mt = 0; mt < 2; mt++)
        #pragma unroll
        for (int nt = 0; nt < 4; nt++)
            #pragma unroll
            for (int q = 0; q < 4; q++) acc[mt][nt][q] = 0.0f;

    const int arow = ctx.arow, aq = ctx.aq;
    float4 av[4];
    float  asc;
    uint4  b0[8], b1[8];

    // prologue: A[0] staged, B[0] -> b0
    {
        int src = s_srcs[arow * PK + 0];
        asc = s_coef[arow * PK + 0];
        const float4* xp = (const float4*)(x + (size_t)src * IN_F + aq * 16);
        #pragma unroll
        for (int j = 0; j < 4; j++) av[j] = xp[j];
        b_prefetch(b0, g_bfrag + wnp * 1024 + lane * 8);
        A_CVT_STORE(0);
    }
    __syncthreads();

    #pragma unroll 1
    for (int kk = 0; kk < PK; kk += 2) {
        gemm_step(kk,     b0, b1, ctx, av, asc, acc);
        gemm_step(kk + 1, b1, b0, ctx, av, asc, acc);
    }

    // ---- epilogue ----
    #pragma unroll
    for (int mt = 0; mt < 2; mt++) {
        int row = c0 + mt * 16 + (lane >> 2);
        #pragma unroll
        for (int nt = 0; nt < 4; nt++) {
            int col = wnp * 32 + nt * 8 + (lane & 3) * 2;
            float2 v0 = make_float2(acc[mt][nt][0], acc[mt][nt][1]);
            float2 v1 = make_float2(acc[mt][nt][2], acc[mt][nt][3]);
            *(float2*)(out + (size_t)row * OUT_F + col)       = v0;
            *(float2*)(out + (size_t)(row + 8) * OUT_F + col) = v1;
        }
    }
}

extern "C" void kernel_launch(void* const* d_in, const int* in_sizes, int n_in,
                              void* d_out, int out_size) {
    const float* x             = (const float*)d_in[0];
    const float* pos           = (const float*)d_in[1];
    const int*   edge_src      = (const int*)d_in[2];
    const int*   edge_tgt      = (const int*)d_in[3];
    const float* kernel_pts    = (const float*)d_in[4];
    const float* kernel_weight = (const float*)d_in[5];
    float* out = (float*)d_out;

    wpack_kernel<<<(PK * 4 * 4 * 32 * 8 + 255) / 256, 256>>>(kernel_weight);

    cudaFuncSetAttribute(kpconv_hmma_kernel,
                         cudaFuncAttributeMaxDynamicSharedMemorySize, SM_TOTAL);
    kpconv_hmma_kernel<<<NCENT / M_TILE, NTH, SM_TOTAL>>>(
        x, pos, edge_src, edge_tgt, kernel_pts, out);
}

// round 16
// speedup vs baseline: 1.7696x; 1.0964x over previous
#include <cuda_runtime.h>
#include <cuda_fp16.h>
#include <cstdint>

#define PK      16
#define NCENT   8192
#define IN_F    64
#define OUT_F   128
#define M_TILE  16
#define NTH     128
#define LDB     144          // A smem row pitch bytes (64 fp16 + 8 pad)

// B packed in mma-fragment order (PTX m16n8k16 .col B frag), fp16 single:
// index = k*4096 + wn4*1024 + nt4*256 + lane*8 + r   (u32 units)
//   r = ks*2 + pair; element = half2{ W[k][i][o], W[k][i+1][o] }
//   o = wn*32 + nt*8 + (lane>>2);  i = ks*16 + (lane&3)*2 + pair*8
__device__ __align__(128) uint32_t g_bfrag[PK * 4 * 4 * 32 * 8];   // 256KB

// ---------------- smem layout (bytes): A double-buffered, 7KB/CTA -----------
#define SM_KPTS   0                        // 48 floats
#define SM_COEF   256                      // 16*16 f32 = 1024
#define SM_SRCS   (SM_COEF + 1024)         // 16*16 int = 1024
#define SM_A      2432
#define A_BYTES   (M_TILE * LDB)           // 2304
#define AH_OFF(s) (SM_A + (s) * A_BYTES)
#define SM_TOTAL  (SM_A + 2 * A_BYTES)     // 7040

__device__ __forceinline__ uint32_t smem_u32(const void* p) {
    uint32_t a;
    asm("{ .reg .u64 t; cvta.to.shared.u64 t, %1; cvt.u32.u64 %0, t; }"
        : "=r"(a) : "l"(p));
    return a;
}
__device__ __forceinline__ void ldsm4(uint32_t* r, uint32_t addr) {
    asm volatile("ldmatrix.sync.aligned.m8n8.x4.shared.b16 {%0,%1,%2,%3}, [%4];"
                 : "=r"(r[0]), "=r"(r[1]), "=r"(r[2]), "=r"(r[3]) : "r"(addr));
}
__device__ __forceinline__ void mma_f16(float* c, const uint32_t* a, const uint32_t* b) {
    asm volatile("mma.sync.aligned.m16n8k16.row.col.f32.f16.f16.f32 "
                 "{%0,%1,%2,%3}, {%4,%5,%6,%7}, {%8,%9}, {%0,%1,%2,%3};"
                 : "+f"(c[0]), "+f"(c[1]), "+f"(c[2]), "+f"(c[3])
                 : "r"(a[0]), "r"(a[1]), "r"(a[2]), "r"(a[3]),
                   "r"(b[0]), "r"(b[1]));
}

// ---------------- pre-kernel: W -> fragment-packed fp16 ----------------------
__global__ void wpack_kernel(const float* __restrict__ w) {
    int idx = blockIdx.x * blockDim.x + threadIdx.x;
    if (idx >= PK * 4 * 4 * 32 * 8) return;     // 65536
    int r    = idx & 7;
    int lane = (idx >> 3) & 31;
    int nt   = (idx >> 8) & 3;
    int wn   = (idx >> 10) & 3;
    int k    = idx >> 12;
    int ks   = r >> 1;
    int pair = r & 1;
    int o = wn * 32 + nt * 8 + (lane >> 2);
    int i = ks * 16 + (lane & 3) * 2 + pair * 8;
    float v0 = w[k * (IN_F * OUT_F) + i * OUT_F + o];
    float v1 = w[k * (IN_F * OUT_F) + (i + 1) * OUT_F + o];
    __half2 p; p.x = __float2half(v0); p.y = __float2half(v1);
    g_bfrag[idx] = *(uint32_t*)&p;
}

// A staging: thread owns row arow = tid>>3 (0..15), 8-float chunk aq = tid&7
#define A_CVT_STORE(stage)                                                  \
    do {                                                                    \
        float fv[8];                                                        \
        fv[0] = av[0].x * asc; fv[1] = av[0].y * asc;                       \
        fv[2] = av[0].z * asc; fv[3] = av[0].w * asc;                       \
        fv[4] = av[1].x * asc; fv[5] = av[1].y * asc;                       \
        fv[6] = av[1].z * asc; fv[7] = av[1].w * asc;                       \
        uint32_t hi[4];                                                     \
        _Pragma("unroll")                                                   \
        for (int e2 = 0; e2 < 4; e2++) {                                    \
            __half2 hp;                                                     \
            hp.x = __float2half(fv[e2 * 2]);                                \
            hp.y = __float2half(fv[e2 * 2 + 1]);                            \
            hi[e2] = *(uint32_t*)&hp;                                       \
        }                                                                   \
        *(uint4*)(sm + AH_OFF(stage) + arow * LDB + aq * 16) =              \
            make_uint4(hi[0], hi[1], hi[2], hi[3]);                         \
    } while (0)

// B prefetch: 8 uint4 = 4 nt-tiles x (8 u32)
__device__ __forceinline__ void b_prefetch(uint4 (&b)[8], const uint32_t* bb) {
    b[0] = *(const uint4*)(bb + 0);    b[1] = *(const uint4*)(bb + 4);
    b[2] = *(const uint4*)(bb + 256);  b[3] = *(const uint4*)(bb + 260);
    b[4] = *(const uint4*)(bb + 512);  b[5] = *(const uint4*)(bb + 516);
    b[6] = *(const uint4*)(bb + 768);  b[7] = *(const uint4*)(bb + 772);
}

struct StepCtx {
    char* sm; uint32_t smb;
    const float* x; const int* s_srcs; const float* s_coef;
    int arow, aq, wnp, lane;
    uint32_t a_row_off;
};

__device__ __forceinline__ void gemm_step(
    int k, uint4 (&bcur)[8], uint4 (&bnxt)[8],
    const StepCtx& c, float4 (&av)[2], float& asc,
    float (&acc)[4][4])
{
    char* sm = c.sm;
    const int arow = c.arow, aq = c.aq;
    const int cur = k & 1;

    // prefetch A[k+1] + B[k+1] (LDGs outstanding across compute)
    if (k + 1 < PK) {
        int src = c.s_srcs[arow * PK + k + 1];
        asc = c.s_coef[arow * PK + k + 1];
        const float4* xp = (const float4*)(c.x + (size_t)src * IN_F + aq * 8);
        av[0] = xp[0]; av[1] = xp[1];
        b_prefetch(bnxt, g_bfrag + (k + 1) * 4096 + c.wnp * 1024 + c.lane * 8);
    }

    // unpack current B fragments (register aliases)
    uint32_t bh[4][8];
    #pragma unroll
    for (int j = 0; j < 4; j++) {
        bh[j][0] = bcur[2*j].x;   bh[j][1] = bcur[2*j].y;
        bh[j][2] = bcur[2*j].z;   bh[j][3] = bcur[2*j].w;
        bh[j][4] = bcur[2*j+1].x; bh[j][5] = bcur[2*j+1].y;
        bh[j][6] = bcur[2*j+1].z; bh[j][7] = bcur[2*j+1].w;
    }

    const uint32_t ah_b = c.smb + AH_OFF(cur);
    #pragma unroll
    for (int ks = 0; ks < 4; ks++) {
        const uint32_t i0 = ks * 32;
        uint32_t ah[4];
        ldsm4(ah, ah_b + c.a_row_off + i0);
        #pragma unroll
        for (int nt = 0; nt < 4; nt++)
            mma_f16(acc[nt], ah, &bh[nt][ks * 2]);
    }

    if (k + 1 < PK) A_CVT_STORE(cur ^ 1);
    __syncthreads();
}

// ---------------- main fused kernel ------------------------------------------
__global__ __launch_bounds__(NTH, 4) void kpconv_hmma_kernel(
    const float* __restrict__ x,
    const float* __restrict__ pos,
    const int*   __restrict__ edge_src,
    const int*   __restrict__ edge_tgt,
    const float* __restrict__ kernel_pts,
    float* __restrict__ out)
{
    extern __shared__ char sm[];
    const uint32_t smb = smem_u32(sm);
    float* s_kpts = (float*)(sm + SM_KPTS);
    float* s_coef = (float*)(sm + SM_COEF);
    int*   s_srcs = (int*)(sm + SM_SRCS);

    const int tid  = threadIdx.x;
    const int wid  = tid >> 5;
    const int lane = tid & 31;
    const int c0   = blockIdx.x * M_TILE;

    if (tid < PK * 3) s_kpts[tid] = kernel_pts[tid];
    for (int i = tid; i < M_TILE * PK; i += NTH) s_coef[i] = 0.0f;
    __syncthreads();

    // ---- geometry: argmin kernel point + linear influence -> coef/srcs -----
    #pragma unroll
    for (int j = 0; j < (M_TILE * PK) / NTH; j++) {
        int el = tid + j * NTH;                 // local edge 0..255
        int e  = c0 * PK + el;
        int s  = edge_src[e];
        int t  = edge_tgt[e];
        s_srcs[el] = s;
        float rx = pos[3 * t + 0] - pos[3 * s + 0];
        float ry = pos[3 * t + 1] - pos[3 * s + 1];
        float rz = pos[3 * t + 2] - pos[3 * s + 2];
        float best = 3.4e38f; int bk = 0;
        #pragma unroll
        for (int kp = 0; kp < PK; kp++) {
            float dx = rx - s_kpts[3 * kp + 0];
            float dy = ry - s_kpts[3 * kp + 1];
            float dz = rz - s_kpts[3 * kp + 2];
            float d2 = dx * dx + dy * dy + dz * dz;
            if (d2 < best) { best = d2; bk = kp; }
        }
        float w = fmaxf(1.0f - sqrtf(best) * 1.5f, 0.0f);   // 1/KP_EXTENT = 1.5
        atomicAdd(&s_coef[(el & ~(PK - 1)) + bk], w);
    }
    __syncthreads();

    // 4 warps, each owns the full 16 rows x 32 cols (wnp = wid)
    const int wnp = wid;

    StepCtx ctx;
    ctx.sm = sm; ctx.smb = smb;
    ctx.x = x; ctx.s_srcs = s_srcs; ctx.s_coef = s_coef;
    ctx.arow = tid >> 3; ctx.aq = tid & 7; ctx.wnp = wnp; ctx.lane = lane;
    ctx.a_row_off = (uint32_t)((lane & 15) * LDB + (lane >> 4) * 16);

    float acc[4][4];
    #pragma unroll
    for (int nt = 0; nt < 4; nt++)
        #pragma unroll
        for (int q = 0; q < 4; q++) acc[nt][q] = 0.0f;

    const int arow = ctx.arow, aq = ctx.aq;
    float4 av[2];
    float  asc;
    uint4  b0[8], b1[8];

    // prologue: A[0] staged, B[0] -> b0
    {
        int src = s_srcs[arow * PK + 0];
        asc = s_coef[arow * PK + 0];
        const float4* xp = (const float4*)(x + (size_t)src * IN_F + aq * 8);
        av[0] = xp[0]; av[1] = xp[1];
        b_prefetch(b0, g_bfrag + wnp * 1024 + lane * 8);
        A_CVT_STORE(0);
    }
    __syncthreads();

    #pragma unroll 1
    for (int kk = 0; kk < PK; kk += 2) {
        gemm_step(kk,     b0, b1, ctx, av, asc, acc);
        gemm_step(kk + 1, b1, b0, ctx, av, asc, acc);
    }

    // ---- epilogue: direct f32 stores ----------------------------------------
    {
        int row = c0 + (lane >> 2);
        #pragma unroll
        for (int nt = 0; nt < 4; nt++) {
            int col = wnp * 32 + nt * 8 + (lane & 3) * 2;
            float2 v0 = make_float2(acc[nt][0], acc[nt][1]);
            float2 v1 = make_float2(acc[nt][2], acc[nt][3]);
            *(float2*)(out + (size_t)row * OUT_F + col)       = v0;
            *(float2*)(out + (size_t)(row + 8) * OUT_F + col) = v1;
        }
    }
}

extern "C" void kernel_launch(void* const* d_in, const int* in_sizes, int n_in,
                              void* d_out, int out_size) {
    const float* x             = (const float*)d_in[0];
    const float* pos           = (const float*)d_in[1];
    const int*   edge_src      = (const int*)d_in[2];
    const int*   edge_tgt      = (const int*)d_in[3];
    const float* kernel_pts    = (const float*)d_in[4];
    const float* kernel_weight = (const float*)d_in[5];
    float* out = (float*)d_out;

    wpack_kernel<<<(PK * 4 * 4 * 32 * 8 + 255) / 256, 256>>>(kernel_weight);

    cudaFuncSetAttribute(kpconv_hmma_kernel,
                         cudaFuncAttributeMaxDynamicSharedMemorySize, SM_TOTAL);
    kpconv_hmma_kernel<<<NCENT / M_TILE, NTH, SM_TOTAL>>>(
        x, pos, edge_src, edge_tgt, kernel_pts, out);
}